// round 16
// baseline (speedup 1.0000x reference)
#include <cuda_runtime.h>
#include <cuda_fp16.h>
#include <math.h>
#include <stdint.h>

// Problem constants
#define BN 16
#define DDIM 256
#define TT 2048
#define KK 1024
#define NPTS (BN*TT)        // 32768 points
#define NQ (BN*DDIM*TT)     // 8388608 elements
#define CUT 3e-4f           // shortlist cut: ~17+ sigma of fp16-GEMM + f16-store noise

// ---------------- Device scratch ----------------
__device__ __half g_xh[(size_t)NPTS * DDIM];    // fp16 x, point-major
__device__ float  g_xt[(size_t)NPTS * DDIM];    // fp32 x, point-major
__device__ __half g_eh[KK * DDIM];              // fp16 embeddings
__device__ __half g_scores[(size_t)NPTS * KK];  // 64MB score matrix
__device__ float  g_minph[(size_t)NPTS * 16];   // per-(point, wn, phase) score mins
__device__ float  g_c2[KK];
__device__ int    g_enc[NPTS];
__device__ double g_bsum[8192];

// ---------------- baseline-PTX helpers ----------------
__device__ __forceinline__ uint32_t smem_u32(const void* p) {
    uint32_t a;
    asm("{ .reg .u64 t; cvta.to.shared.u64 t, %1; cvt.u32.u64 %0, t; }" : "=r"(a) : "l"(p));
    return a;
}
__device__ __forceinline__ void cpasync16(uint32_t dst, const void* src) {
    asm volatile("cp.async.cg.shared.global [%0], [%1], 16;"
                 :: "r"(dst), "l"(__cvta_generic_to_global(src)) : "memory");
}
#define CP_COMMIT() asm volatile("cp.async.commit_group;" ::: "memory")
#define CP_WAIT0()  asm volatile("cp.async.wait_group 0;" ::: "memory")

__device__ __forceinline__ void ldm_x4(uint32_t a, uint32_t& r0, uint32_t& r1,
                                       uint32_t& r2, uint32_t& r3) {
    asm volatile("ldmatrix.sync.aligned.m8n8.x4.shared.b16 {%0,%1,%2,%3}, [%4];"
                 : "=r"(r0), "=r"(r1), "=r"(r2), "=r"(r3) : "r"(a));
}
__device__ __forceinline__ void mma_f16(float* d, const uint32_t* a,
                                        uint32_t b0, uint32_t b1) {
    asm volatile("mma.sync.aligned.m16n8k16.row.col.f32.f16.f16.f32 "
                 "{%0,%1,%2,%3}, {%4,%5,%6,%7}, {%8,%9}, {%0,%1,%2,%3};"
                 : "+f"(d[0]), "+f"(d[1]), "+f"(d[2]), "+f"(d[3])
                 : "r"(a[0]), "r"(a[1]), "r"(a[2]), "r"(a[3]), "r"(b0), "r"(b1));
}
__device__ __forceinline__ bool lex_lt(float a, int i, float b, int j) {
    return a < b || (a == b && i < j);
}

// ---------------- prep: fp16 casts + ||e||^2 ----------------
__global__ __launch_bounds__(256) void k_prep_e(const float* __restrict__ emb) {
    __shared__ float red[256];
    int k = blockIdx.x, d = threadIdx.x;
    float v = emb[k * DDIM + d];
    g_eh[k * DDIM + d] = __float2half_rn(v);
    red[d] = v * v;
    __syncthreads();
    for (int off = 128; off > 0; off >>= 1) {
        if (d < off) red[d] += red[d + off];
        __syncthreads();
    }
    if (d == 0) g_c2[k] = red[0];
}

// x [B,D,T] -> point-major fp16 + fp32
__global__ __launch_bounds__(256) void k_prep_x(const float* __restrict__ x) {
    __shared__ float tile[32][33];
    int t0 = blockIdx.x * 32, d0 = blockIdx.y * 32, b = blockIdx.z;
    int tx = threadIdx.x, ty = threadIdx.y;
    #pragma unroll
    for (int j = 0; j < 4; j++) {
        int r = ty + j * 8;
        tile[r][tx] = x[((size_t)(b * DDIM + d0 + r)) * TT + t0 + tx];
    }
    __syncthreads();
    #pragma unroll
    for (int j = 0; j < 4; j++) {
        int r = ty + j * 8;
        size_t n = (size_t)b * TT + t0 + r;
        float v = tile[tx][r];
        g_xh[n * DDIM + d0 + tx] = __float2half_rn(v);
        g_xt[n * DDIM + d0 + tx] = v;
    }
}

// ---------------- Pass A: fp16 GEMM -> f16 scores + per-phase mins ----------------
#define ROWB 80                  // bytes per smem row (32 b16 + 8 pad)
#define MATB (128 * ROWB)        // 10240 B per matrix chunk
#define BUFB (2 * MATB)          // X, E = 20480
#define C2OFF (2 * BUFB)         // 40960
#define GEMM_DSMEM (C2OFF + KK * 4)   // 45056

__device__ __forceinline__ void issue_chunk(int q, uint32_t base, int tid, int m0) {
    int ph = q >> 3, kc = q & 7;
    const __half* xh = g_xh + (size_t)m0 * DDIM;
    const __half* eh = g_eh + (size_t)(ph * 128) * DDIM;
    #pragma unroll
    for (int it = 0; it < 2; it++) {
        int idx = tid + it * 256;          // 0..511
        int row = idx >> 2, c16 = idx & 3;
        int gof = row * DDIM + kc * 32 + c16 * 8;
        uint32_t so = (uint32_t)(row * ROWB + c16 * 16);
        cpasync16(base + 0 * MATB + so, xh + gof);
        cpasync16(base + 1 * MATB + so, eh + gof);
    }
}

__global__ void __launch_bounds__(256, 2) k_gemm() {
    extern __shared__ char dsm[];
    const uint32_t smb = smem_u32(dsm);
    float* c2s = (float*)(dsm + C2OFF);

    const int tid = threadIdx.x;
    const int wid = tid >> 5;
    const int lane = tid & 31;
    const int wm = wid >> 1;       // 0..3 (M, 32 rows)
    const int wn = wid & 1;        // 0..1 (N, 64 codes)
    const int m0 = blockIdx.x * 128;

    for (int i = tid; i < KK; i += 256) c2s[i] = g_c2[i];

    const int a_row = lane & 15;
    const int a_c8  = (lane >> 4) * 8;
    const int b_row4  = lane & 7;
    const int b_c84   = ((lane >> 3) & 1) * 8;
    const int b_ntoff = lane >> 4;

    issue_chunk(0, smb, tid, m0);
    CP_COMMIT();
    int buf = 0;

    for (int ph = 0; ph < 8; ph++) {
        float acc[2][8][4];
        #pragma unroll
        for (int mt = 0; mt < 2; mt++)
            #pragma unroll
            for (int nt = 0; nt < 8; nt++)
                #pragma unroll
                for (int r = 0; r < 4; r++) acc[mt][nt][r] = 0.f;

        for (int kc = 0; kc < 8; kc++) {
            CP_WAIT0();
            __syncthreads();
            int q = ph * 8 + kc;
            if (q < 63) {
                issue_chunk(q + 1, smb + (uint32_t)((buf ^ 1) * BUFB), tid, m0);
                CP_COMMIT();
            }

            const uint32_t ab = smb + (uint32_t)(buf * BUFB);
            const uint32_t bb = ab + MATB;

            #pragma unroll
            for (int ks = 0; ks < 2; ks++) {
                const int kb = ks * 16;
                uint32_t ao0 = (uint32_t)((wm * 32 + a_row) * ROWB + (kb + a_c8) * 2);
                uint32_t ao1 = (uint32_t)((wm * 32 + 16 + a_row) * ROWB + (kb + a_c8) * 2);
                uint32_t a0[4], a1[4];
                ldm_x4(ab + ao0, a0[0], a0[1], a0[2], a0[3]);
                ldm_x4(ab + ao1, a1[0], a1[1], a1[2], a1[3]);

                uint32_t bf[8][2];
                #pragma unroll
                for (int jj = 0; jj < 4; jj++) {
                    int ntp = jj * 2;
                    uint32_t bo = (uint32_t)((wn * 64 + (ntp + b_ntoff) * 8 + b_row4) * ROWB
                                             + (kb + b_c84) * 2);
                    ldm_x4(bb + bo, bf[ntp][0], bf[ntp][1], bf[ntp+1][0], bf[ntp+1][1]);
                }
                #pragma unroll
                for (int j = 0; j < 8; j++) {
                    mma_f16(acc[0][j], a0, bf[j][0], bf[j][1]);
                    mma_f16(acc[1][j], a1, bf[j][0], bf[j][1]);
                }
            }
            __syncthreads();
            buf ^= 1;
        }

        // epilogue: f16 score store + branch-free per-slot min + phase-min store
        #pragma unroll
        for (int mt = 0; mt < 2; mt++) {
            #pragma unroll
            for (int h = 0; h < 2; h++) {
                int row = m0 + wm * 32 + mt * 16 + h * 8 + (lane >> 2);
                __half2* dst = (__half2*)(g_scores + (size_t)row * KK);
                float smin = 1e30f;
                #pragma unroll
                for (int nt = 0; nt < 8; nt++) {
                    int k0 = ph * 128 + wn * 64 + nt * 8 + (lane & 3) * 2;
                    float s0 = fmaf(-2.f, acc[mt][nt][2 * h + 0], c2s[k0]);
                    float s1 = fmaf(-2.f, acc[mt][nt][2 * h + 1], c2s[k0 + 1]);
                    dst[k0 >> 1] = __floats2half2_rn(s0, s1);
                    smin = fminf(smin, fminf(s0, s1));
                }
                smin = fminf(smin, __shfl_xor_sync(0xffffffffu, smin, 1));
                smin = fminf(smin, __shfl_xor_sync(0xffffffffu, smin, 2));
                if ((lane & 3) == 0)
                    g_minph[(size_t)row * 16 + wn * 8 + ph] = smin;
            }
        }
    }
}

// ---------------- k_select v3: phase-min filter, tiny score reads ----------------
__global__ __launch_bounds__(256) void k_select(const float* __restrict__ emb) {
    __shared__ int s_cnt[8];
    __shared__ int s_list[8][64];
    const int wip = threadIdx.x >> 5;
    const int lane = threadIdx.x & 31;
    const int n = blockIdx.x * 8 + wip;

    // phase mins (min over the two wn halves)
    float pm = 1e30f;
    if (lane < 8) {
        float a = g_minph[(size_t)n * 16 + lane];
        float b = g_minph[(size_t)n * 16 + 8 + lane];
        pm = fminf(a, b);
    }
    float m = pm;
    #pragma unroll
    for (int off = 16; off > 0; off >>= 1)
        m = fminf(m, __shfl_xor_sync(0xffffffffu, m, off));
    const float cut = m + CUT;
    unsigned pmask = __ballot_sync(0xffffffffu, lane < 8 && pm <= cut);

    if (lane == 0) s_cnt[wip] = 0;
    __syncwarp();

    // scan only flagged phases (usually 1): 128 scores = 2 half2 per lane
    int cnt = 0;
    float bs = 1e30f; int bk = KK;
    unsigned mask = pmask;
    while (mask) {
        int p = __ffs(mask) - 1;
        mask &= mask - 1;
        const __half2* sp = (const __half2*)(g_scores + (size_t)n * KK) + p * 64;
        #pragma unroll
        for (int i = 0; i < 2; i++) {
            float2 v = __half22float2(sp[lane + i * 32]);
            int k0 = p * 128 + (lane + i * 32) * 2;
            if (v.x <= cut) {
                cnt++;
                if (lex_lt(v.x, k0, bs, bk)) { bs = v.x; bk = k0; }
                int q = atomicAdd(&s_cnt[wip], 1);
                if (q < 64) s_list[wip][q] = k0;
            }
            if (v.y <= cut) {
                cnt++;
                if (lex_lt(v.y, k0 + 1, bs, bk)) { bs = v.y; bk = k0 + 1; }
                int q = atomicAdd(&s_cnt[wip], 1);
                if (q < 64) s_list[wip][q] = k0 + 1;
            }
        }
    }
    #pragma unroll
    for (int off = 16; off > 0; off >>= 1) {
        cnt += __shfl_xor_sync(0xffffffffu, cnt, off);
        float os = __shfl_xor_sync(0xffffffffu, bs, off);
        int   ok = __shfl_xor_sync(0xffffffffu, bk, off);
        if (lex_lt(os, ok, bs, bk)) { bs = os; bk = ok; }
    }
    __syncwarp();

    if (cnt == 1) {
        if (lane == 0) g_enc[n] = bk;
        return;
    }

    // multi-candidate (~4% of points): exact fp64 over shortlist
    int c = s_cnt[wip];
    bool overflow = (c > 64);
    if (overflow) c = KK;   // exhaustive fallback (practically never)

    const float* xr = g_xt + (size_t)n * DDIM;
    double xv[8];
    #pragma unroll
    for (int j = 0; j < 8; j++) xv[j] = (double)xr[j * 32 + lane];

    double bd = 1e300;
    int    bbk = KK;
    for (int ci = 0; ci < c; ci++) {
        int k = overflow ? ci : s_list[wip][ci];
        const float* er = emb + (size_t)k * DDIM;
        double a = 0.0;
        #pragma unroll
        for (int j = 0; j < 8; j++) {
            double f = xv[j] - (double)er[j * 32 + lane];
            a = fma(f, f, a);
        }
        #pragma unroll
        for (int off = 16; off > 0; off >>= 1)
            a += __shfl_down_sync(0xffffffffu, a, off);
        if (lane == 0) {
            if (a < bd || (a == bd && k < bbk)) { bd = a; bbk = k; }
        }
    }
    if (lane == 0) g_enc[n] = bbk;
}

// ---------------- quantized_st + MSE partials ----------------
__global__ __launch_bounds__(256) void k_quant(const float* __restrict__ x,
                                               const float* __restrict__ emb,
                                               float* __restrict__ out,
                                               int do_store) {
    __shared__ float sf[256];
    const int tid = threadIdx.x;
    const int gi = blockIdx.x * 256 + tid;
    const size_t base = (size_t)gi * 4;

    int t = (int)(base % TT);
    size_t tmp = base / TT;
    int d = (int)(tmp % DDIM);
    int b = (int)(tmp / DDIM);

    float4 xv = *(const float4*)&x[base];
    int nb = b * TT + t;
    int i0 = g_enc[nb + 0];
    int i1 = g_enc[nb + 1];
    int i2 = g_enc[nb + 2];
    int i3 = g_enc[nb + 3];
    float q0 = __ldg(&emb[i0 * DDIM + d]);
    float q1 = __ldg(&emb[i1 * DDIM + d]);
    float q2 = __ldg(&emb[i2 * DDIM + d]);
    float q3 = __ldg(&emb[i3 * DDIM + d]);
    float d0 = q0 - xv.x;
    float d1 = q1 - xv.y;
    float d2 = q2 - xv.z;
    float d3 = q3 - xv.w;
    if (do_store) {
        float4 ov = make_float4(xv.x + d0, xv.y + d1, xv.z + d2, xv.w + d3);
        *(float4*)&out[base] = ov;
    }
    float loc = d0 * d0;
    loc = fmaf(d1, d1, loc);
    loc = fmaf(d2, d2, loc);
    loc = fmaf(d3, d3, loc);

    sf[tid] = loc;
    __syncthreads();
    for (int off = 128; off > 0; off >>= 1) {
        if (tid < off) sf[tid] += sf[tid + off];
        __syncthreads();
    }
    if (tid == 0) g_bsum[blockIdx.x] = (double)sf[0];
}

// Block 0: deterministic final MSE reduce + scalars. Blocks 1..128: indices.
__global__ void k_finish(float* __restrict__ out, int out_size) {
    if (blockIdx.x == 0) {
        __shared__ double sd[256];
        const int tid = threadIdx.x;
        double loc = 0.0;
        for (int i = tid; i < 8192; i += 256) loc += g_bsum[i];
        sd[tid] = loc;
        __syncthreads();
        for (int off = 128; off > 0; off >>= 1) {
            if (tid < off) sd[tid] += sd[tid + off];
            __syncthreads();
        }
        if (tid == 0 && out_size >= NQ + 3) {
            float mse = (float)(sd[0] / (double)NQ);
            out[NQ + 0] = mse + 0.25f * mse;
            out[NQ + 1] = mse;
            out[NQ + 2] = mse;
        }
    } else {
        int i = (blockIdx.x - 1) * 256 + threadIdx.x;
        if (i < NPTS && out_size >= NQ + 3 + NPTS)
            out[NQ + 3 + i] = (float)g_enc[i];
    }
}

extern "C" void kernel_launch(void* const* d_in, const int* in_sizes, int n_in,
                              void* d_out, int out_size) {
    const float* x   = (const float*)d_in[0];
    const float* emb = (const float*)d_in[1];
    if (n_in >= 2 && in_sizes[0] == KK * DDIM && in_sizes[1] == NQ) {
        const float* tmp = x; x = emb; emb = tmp;
    }
    float* out = (float*)d_out;
    int do_store = (out_size >= NQ) ? 1 : 0;

    static int attr_set = 0;
    if (!attr_set) {
        cudaFuncSetAttribute(k_gemm, cudaFuncAttributeMaxDynamicSharedMemorySize, GEMM_DSMEM);
        attr_set = 1;
    }

    k_prep_e<<<KK, 256>>>(emb);
    k_prep_x<<<dim3(TT / 32, DDIM / 32, BN), dim3(32, 8)>>>(x);
    k_gemm<<<NPTS / 128, 256, GEMM_DSMEM>>>();
    k_select<<<NPTS / 8, 256>>>(emb);            // 4th launch -> profiled
    k_quant<<<NQ / (256 * 4), 256>>>(x, emb, out, do_store);
    k_finish<<<1 + NPTS / 256, 256>>>(out, out_size);
}

// round 17
// speedup vs baseline: 1.0355x; 1.0355x over previous
#include <cuda_runtime.h>
#include <cuda_fp16.h>
#include <math.h>
#include <stdint.h>

// Problem constants
#define BN 16
#define DDIM 256
#define TT 2048
#define KK 1024
#define NPTS (BN*TT)        // 32768 points
#define NQ (BN*DDIM*TT)     // 8388608 elements
#define CUT 3e-4f           // shortlist cut: ~17+ sigma of fp16-GEMM + f16-store noise

// ---------------- Device scratch ----------------
__device__ __half g_xh[(size_t)NPTS * DDIM];    // fp16 x, point-major
__device__ __half g_eh[KK * DDIM];              // fp16 embeddings
__device__ __half g_scores[(size_t)NPTS * KK];  // 64MB score matrix
__device__ float  g_c2[KK];
__device__ int    g_enc[NPTS];
__device__ double g_bsum[8192];

// ---------------- baseline-PTX helpers ----------------
__device__ __forceinline__ uint32_t smem_u32(const void* p) {
    uint32_t a;
    asm("{ .reg .u64 t; cvta.to.shared.u64 t, %1; cvt.u32.u64 %0, t; }" : "=r"(a) : "l"(p));
    return a;
}
__device__ __forceinline__ void cpasync16(uint32_t dst, const void* src) {
    asm volatile("cp.async.cg.shared.global [%0], [%1], 16;"
                 :: "r"(dst), "l"(__cvta_generic_to_global(src)) : "memory");
}
#define CP_COMMIT() asm volatile("cp.async.commit_group;" ::: "memory")
#define CP_WAIT0()  asm volatile("cp.async.wait_group 0;" ::: "memory")

__device__ __forceinline__ void ldm_x4(uint32_t a, uint32_t& r0, uint32_t& r1,
                                       uint32_t& r2, uint32_t& r3) {
    asm volatile("ldmatrix.sync.aligned.m8n8.x4.shared.b16 {%0,%1,%2,%3}, [%4];"
                 : "=r"(r0), "=r"(r1), "=r"(r2), "=r"(r3) : "r"(a));
}
__device__ __forceinline__ void mma_f16(float* d, const uint32_t* a,
                                        uint32_t b0, uint32_t b1) {
    asm volatile("mma.sync.aligned.m16n8k16.row.col.f32.f16.f16.f32 "
                 "{%0,%1,%2,%3}, {%4,%5,%6,%7}, {%8,%9}, {%0,%1,%2,%3};"
                 : "+f"(d[0]), "+f"(d[1]), "+f"(d[2]), "+f"(d[3])
                 : "r"(a[0]), "r"(a[1]), "r"(a[2]), "r"(a[3]), "r"(b0), "r"(b1));
}
__device__ __forceinline__ bool lex_lt(float a, int i, float b, int j) {
    return a < b || (a == b && i < j);
}

// ---------------- prep: fp16 casts + ||e||^2 ----------------
__global__ __launch_bounds__(256) void k_prep_e(const float* __restrict__ emb) {
    __shared__ float red[256];
    int k = blockIdx.x, d = threadIdx.x;
    float v = emb[k * DDIM + d];
    g_eh[k * DDIM + d] = __float2half_rn(v);
    red[d] = v * v;
    __syncthreads();
    for (int off = 128; off > 0; off >>= 1) {
        if (d < off) red[d] += red[d + off];
        __syncthreads();
    }
    if (d == 0) g_c2[k] = red[0];
}

// x [B,D,T] -> point-major fp16
__global__ __launch_bounds__(256) void k_prep_x(const float* __restrict__ x) {
    __shared__ float tile[32][33];
    int t0 = blockIdx.x * 32, d0 = blockIdx.y * 32, b = blockIdx.z;
    int tx = threadIdx.x, ty = threadIdx.y;
    #pragma unroll
    for (int j = 0; j < 4; j++) {
        int r = ty + j * 8;
        tile[r][tx] = x[((size_t)(b * DDIM + d0 + r)) * TT + t0 + tx];
    }
    __syncthreads();
    #pragma unroll
    for (int j = 0; j < 4; j++) {
        int r = ty + j * 8;
        size_t n = (size_t)b * TT + t0 + r;
        g_xh[n * DDIM + d0 + tx] = __float2half_rn(tile[tx][r]);
    }
}

// ---------------- Pass A: single-term fp16 GEMM, scores -> f16 matrix ----------------
#define ROWB 80                  // bytes per smem row (32 b16 + 8 pad)
#define MATB (128 * ROWB)        // 10240 B per matrix chunk
#define BUFB (2 * MATB)          // X, E = 20480
#define C2OFF (2 * BUFB)         // 40960
#define GEMM_DSMEM (C2OFF + KK * 4)   // 45056

__device__ __forceinline__ void issue_chunk(int q, uint32_t base, int tid, int m0) {
    int ph = q >> 3, kc = q & 7;
    const __half* xh = g_xh + (size_t)m0 * DDIM;
    const __half* eh = g_eh + (size_t)(ph * 128) * DDIM;
    #pragma unroll
    for (int it = 0; it < 2; it++) {
        int idx = tid + it * 256;          // 0..511
        int row = idx >> 2, c16 = idx & 3;
        int gof = row * DDIM + kc * 32 + c16 * 8;
        uint32_t so = (uint32_t)(row * ROWB + c16 * 16);
        cpasync16(base + 0 * MATB + so, xh + gof);
        cpasync16(base + 1 * MATB + so, eh + gof);
    }
}

__global__ void __launch_bounds__(256, 2) k_gemm() {
    extern __shared__ char dsm[];
    const uint32_t smb = smem_u32(dsm);
    float* c2s = (float*)(dsm + C2OFF);

    const int tid = threadIdx.x;
    const int wid = tid >> 5;
    const int lane = tid & 31;
    const int wm = wid >> 1;       // 0..3 (M, 32 rows)
    const int wn = wid & 1;        // 0..1 (N, 64 codes)
    const int m0 = blockIdx.x * 128;

    for (int i = tid; i < KK; i += 256) c2s[i] = g_c2[i];

    const int a_row = lane & 15;
    const int a_c8  = (lane >> 4) * 8;
    const int b_row4  = lane & 7;
    const int b_c84   = ((lane >> 3) & 1) * 8;
    const int b_ntoff = lane >> 4;

    issue_chunk(0, smb, tid, m0);
    CP_COMMIT();
    int buf = 0;

    for (int ph = 0; ph < 8; ph++) {
        float acc[2][8][4];
        #pragma unroll
        for (int mt = 0; mt < 2; mt++)
            #pragma unroll
            for (int nt = 0; nt < 8; nt++)
                #pragma unroll
                for (int r = 0; r < 4; r++) acc[mt][nt][r] = 0.f;

        for (int kc = 0; kc < 8; kc++) {
            CP_WAIT0();
            __syncthreads();
            int q = ph * 8 + kc;
            if (q < 63) {
                issue_chunk(q + 1, smb + (uint32_t)((buf ^ 1) * BUFB), tid, m0);
                CP_COMMIT();
            }

            const uint32_t ab = smb + (uint32_t)(buf * BUFB);
            const uint32_t bb = ab + MATB;

            #pragma unroll
            for (int ks = 0; ks < 2; ks++) {
                const int kb = ks * 16;
                uint32_t ao0 = (uint32_t)((wm * 32 + a_row) * ROWB + (kb + a_c8) * 2);
                uint32_t ao1 = (uint32_t)((wm * 32 + 16 + a_row) * ROWB + (kb + a_c8) * 2);
                uint32_t a0[4], a1[4];
                ldm_x4(ab + ao0, a0[0], a0[1], a0[2], a0[3]);
                ldm_x4(ab + ao1, a1[0], a1[1], a1[2], a1[3]);

                uint32_t bf[8][2];
                #pragma unroll
                for (int jj = 0; jj < 4; jj++) {
                    int ntp = jj * 2;
                    uint32_t bo = (uint32_t)((wn * 64 + (ntp + b_ntoff) * 8 + b_row4) * ROWB
                                             + (kb + b_c84) * 2);
                    ldm_x4(bb + bo, bf[ntp][0], bf[ntp][1], bf[ntp+1][0], bf[ntp+1][1]);
                }
                #pragma unroll
                for (int j = 0; j < 8; j++) {
                    mma_f16(acc[0][j], a0, bf[j][0], bf[j][1]);
                    mma_f16(acc[1][j], a1, bf[j][0], bf[j][1]);
                }
            }
            __syncthreads();
            buf ^= 1;
        }

        // epilogue: branch-free f16 score store
        #pragma unroll
        for (int mt = 0; mt < 2; mt++) {
            #pragma unroll
            for (int h = 0; h < 2; h++) {
                int row = m0 + wm * 32 + mt * 16 + h * 8 + (lane >> 2);
                __half2* dst = (__half2*)(g_scores + (size_t)row * KK);
                #pragma unroll
                for (int nt = 0; nt < 8; nt++) {
                    int k0 = ph * 128 + wn * 64 + nt * 8 + (lane & 3) * 2;
                    float s0 = fmaf(-2.f, acc[mt][nt][2 * h + 0], c2s[k0]);
                    float s1 = fmaf(-2.f, acc[mt][nt][2 * h + 1], c2s[k0 + 1]);
                    dst[k0 >> 1] = __floats2half2_rn(s0, s1);
                }
            }
        }
    }
}

// ---------------- k_select: scan scores, fast unique path, fp64 on ties ----------------
__global__ __launch_bounds__(256) void k_select(const float* __restrict__ x,
                                                const float* __restrict__ emb) {
    __shared__ int s_cnt[8];
    __shared__ int s_list[8][64];
    const int wip = threadIdx.x >> 5;
    const int lane = threadIdx.x & 31;
    const int n = blockIdx.x * 8 + wip;

    const uint4* sc4 = (const uint4*)(g_scores + (size_t)n * KK);

    // scan: 4 x uint4 per lane (64B), coalesced
    uint32_t raw[16];
    #pragma unroll
    for (int i = 0; i < 4; i++) {
        uint4 v = sc4[lane + i * 32];
        raw[i * 4 + 0] = v.x; raw[i * 4 + 1] = v.y;
        raw[i * 4 + 2] = v.z; raw[i * 4 + 3] = v.w;
    }
    float2 vals[16];
    float m = 1e30f;
    #pragma unroll
    for (int i = 0; i < 16; i++) {
        vals[i] = __half22float2(*(const __half2*)&raw[i]);
        m = fminf(m, fminf(vals[i].x, vals[i].y));
    }
    #pragma unroll
    for (int off = 16; off > 0; off >>= 1)
        m = fminf(m, __shfl_xor_sync(0xffffffffu, m, off));
    const float cut = m + CUT;

    // half2 i holds codes 2*((lane + (i>>2)*32)*4 + (i&3)) + {0,1}
    int cnt = 0;
    float bs = 1e30f; int bk = KK;
    #pragma unroll
    for (int i = 0; i < 16; i++) {
        int k0 = ((lane + (i >> 2) * 32) * 4 + (i & 3)) * 2;
        if (vals[i].x <= cut) {
            cnt++;
            if (lex_lt(vals[i].x, k0, bs, bk)) { bs = vals[i].x; bk = k0; }
        }
        if (vals[i].y <= cut) {
            cnt++;
            if (lex_lt(vals[i].y, k0 + 1, bs, bk)) { bs = vals[i].y; bk = k0 + 1; }
        }
    }
    #pragma unroll
    for (int off = 16; off > 0; off >>= 1) {
        cnt += __shfl_xor_sync(0xffffffffu, cnt, off);
        float os = __shfl_xor_sync(0xffffffffu, bs, off);
        int   ok = __shfl_xor_sync(0xffffffffu, bk, off);
        if (lex_lt(os, ok, bs, bk)) { bs = os; bk = ok; }
    }

    if (cnt == 1) {
        if (lane == 0) g_enc[n] = bk;
        return;
    }

    // multi-candidate (~4% of points): shortlist + exact fp64
    if (lane == 0) s_cnt[wip] = 0;
    __syncwarp();
    #pragma unroll
    for (int i = 0; i < 16; i++) {
        int k0 = ((lane + (i >> 2) * 32) * 4 + (i & 3)) * 2;
        if (vals[i].x <= cut) {
            int p = atomicAdd(&s_cnt[wip], 1);
            if (p < 64) s_list[wip][p] = k0;
        }
        if (vals[i].y <= cut) {
            int p = atomicAdd(&s_cnt[wip], 1);
            if (p < 64) s_list[wip][p] = k0 + 1;
        }
    }
    __syncwarp();
    int c = s_cnt[wip];
    bool overflow = (c > 64);
    if (overflow) c = KK;

    // x strided from original [B,D,T] layout (tiny total volume)
    const int b = n / TT, t = n % TT;
    const float* xb = x + (size_t)b * DDIM * TT + t;
    double xv[8];
    #pragma unroll
    for (int j = 0; j < 8; j++) xv[j] = (double)xb[(size_t)(j * 32 + lane) * TT];

    double bd = 1e300;
    int    bbk = KK;
    for (int ci = 0; ci < c; ci++) {
        int k = overflow ? ci : s_list[wip][ci];
        const float* er = emb + (size_t)k * DDIM;
        double a = 0.0;
        #pragma unroll
        for (int j = 0; j < 8; j++) {
            double f = xv[j] - (double)er[j * 32 + lane];
            a = fma(f, f, a);
        }
        #pragma unroll
        for (int off = 16; off > 0; off >>= 1)
            a += __shfl_down_sync(0xffffffffu, a, off);
        if (lane == 0) {
            if (a < bd || (a == bd && k < bbk)) { bd = a; bbk = k; }
        }
    }
    if (lane == 0) g_enc[n] = bbk;
}

// ---------------- quantized_st + MSE partials ----------------
__global__ __launch_bounds__(256) void k_quant(const float* __restrict__ x,
                                               const float* __restrict__ emb,
                                               float* __restrict__ out,
                                               int do_store) {
    __shared__ float sf[256];
    const int tid = threadIdx.x;
    const int gi = blockIdx.x * 256 + tid;
    const size_t base = (size_t)gi * 4;

    int t = (int)(base % TT);
    size_t tmp = base / TT;
    int d = (int)(tmp % DDIM);
    int b = (int)(tmp / DDIM);

    float4 xv = *(const float4*)&x[base];
    int nb = b * TT + t;
    int i0 = g_enc[nb + 0];
    int i1 = g_enc[nb + 1];
    int i2 = g_enc[nb + 2];
    int i3 = g_enc[nb + 3];
    float q0 = __ldg(&emb[i0 * DDIM + d]);
    float q1 = __ldg(&emb[i1 * DDIM + d]);
    float q2 = __ldg(&emb[i2 * DDIM + d]);
    float q3 = __ldg(&emb[i3 * DDIM + d]);
    float d0 = q0 - xv.x;
    float d1 = q1 - xv.y;
    float d2 = q2 - xv.z;
    float d3 = q3 - xv.w;
    if (do_store) {
        float4 ov = make_float4(xv.x + d0, xv.y + d1, xv.z + d2, xv.w + d3);
        *(float4*)&out[base] = ov;
    }
    float loc = d0 * d0;
    loc = fmaf(d1, d1, loc);
    loc = fmaf(d2, d2, loc);
    loc = fmaf(d3, d3, loc);

    sf[tid] = loc;
    __syncthreads();
    for (int off = 128; off > 0; off >>= 1) {
        if (tid < off) sf[tid] += sf[tid + off];
        __syncthreads();
    }
    if (tid == 0) g_bsum[blockIdx.x] = (double)sf[0];
}

// Block 0: deterministic final MSE reduce + scalars. Blocks 1..128: indices.
__global__ void k_finish(float* __restrict__ out, int out_size) {
    if (blockIdx.x == 0) {
        __shared__ double sd[256];
        const int tid = threadIdx.x;
        double loc = 0.0;
        for (int i = tid; i < 8192; i += 256) loc += g_bsum[i];
        sd[tid] = loc;
        __syncthreads();
        for (int off = 128; off > 0; off >>= 1) {
            if (tid < off) sd[tid] += sd[tid + off];
            __syncthreads();
        }
        if (tid == 0 && out_size >= NQ + 3) {
            float mse = (float)(sd[0] / (double)NQ);
            out[NQ + 0] = mse + 0.25f * mse;
            out[NQ + 1] = mse;
            out[NQ + 2] = mse;
        }
    } else {
        int i = (blockIdx.x - 1) * 256 + threadIdx.x;
        if (i < NPTS && out_size >= NQ + 3 + NPTS)
            out[NQ + 3 + i] = (float)g_enc[i];
    }
}

extern "C" void kernel_launch(void* const* d_in, const int* in_sizes, int n_in,
                              void* d_out, int out_size) {
    const float* x   = (const float*)d_in[0];
    const float* emb = (const float*)d_in[1];
    if (n_in >= 2 && in_sizes[0] == KK * DDIM && in_sizes[1] == NQ) {
        const float* tmp = x; x = emb; emb = tmp;
    }
    float* out = (float*)d_out;
    int do_store = (out_size >= NQ) ? 1 : 0;

    static int attr_set = 0;
    if (!attr_set) {
        cudaFuncSetAttribute(k_gemm, cudaFuncAttributeMaxDynamicSharedMemorySize, GEMM_DSMEM);
        attr_set = 1;
    }

    k_prep_e<<<KK, 256>>>(emb);
    k_prep_x<<<dim3(TT / 32, DDIM / 32, BN), dim3(32, 8)>>>(x);
    k_gemm<<<NPTS / 128, 256, GEMM_DSMEM>>>();
    k_select<<<NPTS / 8, 256>>>(x, emb);         // 4th launch -> profiled
    k_quant<<<NQ / (256 * 4), 256>>>(x, emb, out, do_store);
    k_finish<<<1 + NPTS / 256, 256>>>(out, out_size);
}